// round 13
// baseline (speedup 1.0000x reference)
#include <cuda_runtime.h>
#include <math.h>

#define NQ 4
#define SDIM 16
#define KCOLS 512
#define TPB 256
#define ROWS_PER_BLK 32    // 8 warps x 4 rows/warp

// Fused, barrier-free tail: split-K GEMM (8-lane teams per row) + per-warp
// circuit on lanes 0..3. launch_bounds(256,4) caps regs at 64 -> 32 warps/SM.
__global__ __launch_bounds__(TPB, 4) void qnet_fused_kernel(
    const float* __restrict__ A,       // [B,512]
    const float* __restrict__ pre_w,   // [4,512]
    const float* __restrict__ pre_b,   // [4]
    const float* __restrict__ u3p,     // [4,3]
    const float* __restrict__ post_w,  // [2,4]
    const float* __restrict__ post_b,  // [2]
    float* __restrict__ out,           // [B,2]
    int B)
{
    // Permuted weight layout: column c -> idx = colLane + 8*k + 32*j
    // (cq=c>>2, k=c&3, colLane=cq&7, j=cq>>3): conflict-free broadcast LDS.128.
    __shared__ float4 wsm[KCOLS];
    __shared__ float  g[NQ][8];

    const int tid = threadIdx.x;

    // Stage weights (2 columns per thread, permuted)
    #pragma unroll
    for (int t = 0; t < 2; t++) {
        const int c = tid + t * TPB;
        const int cq = c >> 2, k = c & 3;
        const int idx = (cq & 7) + 8 * k + 32 * (cq >> 3);
        wsm[idx] = make_float4(pre_w[c],
                               pre_w[KCOLS + c],
                               pre_w[2 * KCOLS + c],
                               pre_w[3 * KCOLS + c]);
    }
    // Batch-independent U3 gates
    if (tid < NQ) {
        const int q = tid;
        float th = u3p[q * 3 + 0], ph = u3p[q * 3 + 1], la = u3p[q * 3 + 2];
        float ct, st, cl, sl, cp, sp;
        sincosf(0.5f * th, &st, &ct);
        sincosf(la, &sl, &cl);
        sincosf(ph, &sp, &cp);
        float cpl = cp * cl - sp * sl;
        float spl = sp * cl + cp * sl;
        g[q][0] = ct;
        g[q][1] = -cl * st;  g[q][2] = -sl * st;
        g[q][3] =  cp * st;  g[q][4] =  sp * st;
        g[q][5] =  cpl * ct; g[q][6] =  spl * ct;
        g[q][7] = 0.0f;
    }
    __syncthreads();

    // ================= Phase A: GEMM (8-lane team per row) =================
    const int warp = tid >> 5;
    const int lane = tid & 31;
    const int colLane = lane & 7;           // 0..7 within row-team
    const int rowInWrp = lane >> 3;         // 0..3
    const int rowBase = blockIdx.x * ROWS_PER_BLK + warp * 4;
    const int row = rowBase + rowInWrp;

    float a0 = 0.f, a1 = 0.f, a2 = 0.f, a3 = 0.f;
    {
        const float4* rp = (const float4*)(A + (size_t)row * KCOLS);
        #pragma unroll
        for (int h = 0; h < 2; h++) {
            float4 x[8];                    // 8 loads in flight per wave
            #pragma unroll
            for (int j = 0; j < 8; j++)
                x[j] = rp[colLane + 8 * (h * 8 + j)];
            #pragma unroll
            for (int j = 0; j < 8; j++) {
                const int jj = h * 8 + j;
                const float4* wj = &wsm[32 * jj + colLane];
                float4 w0 = wj[0];
                float4 w1 = wj[8];
                float4 w2 = wj[16];
                float4 w3 = wj[24];
                a0 += x[j].x * w0.x + x[j].y * w1.x + x[j].z * w2.x + x[j].w * w3.x;
                a1 += x[j].x * w0.y + x[j].y * w1.y + x[j].z * w2.y + x[j].w * w3.y;
                a2 += x[j].x * w0.z + x[j].y * w1.z + x[j].z * w2.z + x[j].w * w3.z;
                a3 += x[j].x * w0.w + x[j].y * w1.w + x[j].z * w2.w + x[j].w * w3.w;
            }
        }
    }
    // Butterfly within each 8-lane team -> every lane holds its row's sums
    #pragma unroll
    for (int off = 4; off; off >>= 1) {
        a0 += __shfl_xor_sync(0xffffffffu, a0, off);
        a1 += __shfl_xor_sync(0xffffffffu, a1, off);
        a2 += __shfl_xor_sync(0xffffffffu, a2, off);
        a3 += __shfl_xor_sync(0xffffffffu, a3, off);
    }

    // Gather: lane l (<4) takes row rowBase+l from lane 8*l. No smem, no sync.
    const int src = (lane & 3) * 8;
    a0 = __shfl_sync(0xffffffffu, a0, src);
    a1 = __shfl_sync(0xffffffffu, a1, src);
    a2 = __shfl_sync(0xffffffffu, a2, src);
    a3 = __shfl_sync(0xffffffffu, a3, src);

    // ================= Phase B: circuit on lanes 0..3 of each warp =================
    if (lane >= 4) return;
    const int b = rowBase + lane;
    if (b >= B) return;

    float pre[NQ] = {a0 + pre_b[0], a1 + pre_b[1], a2 + pre_b[2], a3 + pre_b[3]};

    float ryc[NQ], rys[NQ], rzc[NQ], rzs[NQ];
    #pragma unroll
    for (int q = 0; q < NQ; q++) {
        float t  = tanhf(pre[q] * 0.1f) * 1.5707963267948966f;
        float ry = atanf(t);
        float rz = atanf(t * t);
        __sincosf(0.5f * ry, &rys[q], &ryc[q]);
        __sincosf(0.5f * rz, &rzs[q], &rzc[q]);
    }

    float re[SDIM], im[SDIM];
    #pragma unroll
    for (int i = 0; i < SDIM; i++) { re[i] = 0.25f; im[i] = 0.0f; }

    // RY layer (state stays real)
    #pragma unroll
    for (int q = 0; q < NQ; q++) {
        const int bit = 8 >> q;
        const float c = ryc[q], s = rys[q];
        #pragma unroll
        for (int i = 0; i < SDIM; i++) {
            if (!(i & bit)) {
                float r0 = re[i], r1 = re[i | bit];
                re[i]       = c * r0 - s * r1;
                re[i | bit] = s * r0 + c * r1;
            }
        }
    }

    // RZ layer
    #pragma unroll
    for (int q = 0; q < NQ; q++) {
        const int bit = 8 >> q;
        const float c = rzc[q], sz = rzs[q];
        #pragma unroll
        for (int i = 0; i < SDIM; i++) {
            float s = (i & bit) ? sz : -sz;
            float r = re[i], m = im[i];
            re[i] = r * c - m * s;
            im[i] = r * s + m * c;
        }
    }

    // CNOT rings (register permutations)
    #define CNOT_(cq, tq)                                                  \
    {                                                                      \
        const int bc = 8 >> (cq), bt = 8 >> (tq);                          \
        _Pragma("unroll")                                                  \
        for (int i = 0; i < SDIM; i++) {                                   \
            if ((i & bc) && !(i & bt)) {                                   \
                float tr = re[i]; re[i] = re[i | bt]; re[i | bt] = tr;     \
                float tm = im[i]; im[i] = im[i | bt]; im[i | bt] = tm;     \
            }                                                              \
        }                                                                  \
    }
    CNOT_(0, 1); CNOT_(1, 2); CNOT_(2, 3); CNOT_(3, 0);
    CNOT_(0, 2); CNOT_(1, 3); CNOT_(2, 0); CNOT_(3, 1);
    #undef CNOT_

    // U3 layer
    #pragma unroll
    for (int q = 0; q < NQ; q++) {
        const int bit = 8 >> q;
        const float g00  = g[q][0];
        const float g01r = g[q][1], g01i = g[q][2];
        const float g10r = g[q][3], g10i = g[q][4];
        const float g11r = g[q][5], g11i = g[q][6];
        #pragma unroll
        for (int i = 0; i < SDIM; i++) {
            if (!(i & bit)) {
                const int j = i | bit;
                float r0 = re[i], m0 = im[i], r1 = re[j], m1 = im[j];
                re[i] = g00 * r0 + g01r * r1 - g01i * m1;
                im[i] = g00 * m0 + g01r * m1 + g01i * r1;
                re[j] = g10r * r0 - g10i * m0 + g11r * r1 - g11i * m1;
                im[j] = g10r * m0 + g10i * r0 + g11r * m1 + g11i * r1;
            }
        }
    }

    // Z expectations
    float e0 = 0.f, e1 = 0.f, e2 = 0.f, e3 = 0.f;
    #pragma unroll
    for (int i = 0; i < SDIM; i++) {
        float p = re[i] * re[i] + im[i] * im[i];
        e0 += (i & 8) ? -p : p;
        e1 += (i & 4) ? -p : p;
        e2 += (i & 2) ? -p : p;
        e3 += (i & 1) ? -p : p;
    }

    float o0 = post_b[0] + e0 * post_w[0] + e1 * post_w[1] + e2 * post_w[2] + e3 * post_w[3];
    float o1 = post_b[1] + e0 * post_w[4] + e1 * post_w[5] + e2 * post_w[6] + e3 * post_w[7];
    ((float2*)out)[b] = make_float2(o0, o1);
}

extern "C" void kernel_launch(void* const* d_in, const int* in_sizes, int n_in,
                              void* d_out, int out_size) {
    const float* A      = (const float*)d_in[0];   // input_features [B,512]
    const float* pre_w  = (const float*)d_in[1];   // [4,512]
    const float* pre_b  = (const float*)d_in[2];   // [4]
    const float* u3p    = (const float*)d_in[3];   // [4,3]
    const float* post_w = (const float*)d_in[4];   // [2,4]
    const float* post_b = (const float*)d_in[5];   // [2]
    float* out          = (float*)d_out;           // [B,2]

    const int B = in_sizes[0] / KCOLS;
    const int grid = (B + ROWS_PER_BLK - 1) / ROWS_PER_BLK;   // 1024
    qnet_fused_kernel<<<grid, TPB>>>(A, pre_w, pre_b, u3p, post_w, post_b, out, B);
}

// round 14
// speedup vs baseline: 1.4714x; 1.4714x over previous
#include <cuda_runtime.h>
#include <math.h>
#include <stdint.h>

#define NQ 4
#define SDIM 16
#define KCOLS 512
#define TPB 256
#define ROWS_PER_BLK 32
#define STAGES 4
#define ROWS_PER_STAGE 8           // 8 warps, 1 row per warp per stage
#define STAGE_BYTES (ROWS_PER_STAGE * KCOLS * 4)   // 16384
#define TILE_BYTES (ROWS_PER_BLK * KCOLS * 4)      // 65536

// dynamic smem layout
#define OFF_TILE  0
#define OFF_W     TILE_BYTES                 // 4 x 512 floats = 8192
#define OFF_PRES  (OFF_W + 8192)             // 32 * float4 = 512
#define OFF_G     (OFF_PRES + 512)           // 4 * 8 floats = 128
#define OFF_MBAR  (OFF_G + 128)              // 4 * 8 bytes
#define SMEM_BYTES (OFF_MBAR + 64)

__device__ __forceinline__ uint32_t smem_u32(const void* p) {
    uint32_t a;
    asm("{ .reg .u64 t; cvta.to.shared.u64 t, %1; cvt.u32.u64 %0, t; }"
        : "=r"(a) : "l"(p));
    return a;
}

__global__ __launch_bounds__(TPB) void qnet_tma_kernel(
    const float* __restrict__ A,       // [B,512]
    const float* __restrict__ pre_w,   // [4,512]
    const float* __restrict__ pre_b,   // [4]
    const float* __restrict__ u3p,     // [4,3]
    const float* __restrict__ post_w,  // [2,4]
    const float* __restrict__ post_b,  // [2]
    float* __restrict__ out,           // [B,2]
    int B)
{
    extern __shared__ char smem[];
    float*  Wf   = (float*)(smem + OFF_W);      // [4][512] de-interleaved
    float4* preS = (float4*)(smem + OFF_PRES);  // [32]
    float*  g    = (float*)(smem + OFF_G);      // [4][8]

    const int tid  = threadIdx.x;
    const int warp = tid >> 5;
    const int lane = tid & 31;

    // ---- stage weights de-interleaved: Wf[r][c] = pre_w[r*512+c] ----
    #pragma unroll
    for (int r = 0; r < 4; r++) {
        Wf[r * KCOLS + tid]       = pre_w[r * KCOLS + tid];
        Wf[r * KCOLS + tid + TPB] = pre_w[r * KCOLS + tid + TPB];
    }
    // ---- batch-independent U3 gates ----
    if (tid < NQ) {
        const int q = tid;
        float th = u3p[q * 3 + 0], ph = u3p[q * 3 + 1], la = u3p[q * 3 + 2];
        float ct, st, cl, sl, cp, sp;
        sincosf(0.5f * th, &st, &ct);
        sincosf(la, &sl, &cl);
        sincosf(ph, &sp, &cp);
        float cpl = cp * cl - sp * sl;
        float spl = sp * cl + cp * sl;
        g[q * 8 + 0] = ct;
        g[q * 8 + 1] = -cl * st;  g[q * 8 + 2] = -sl * st;
        g[q * 8 + 3] =  cp * st;  g[q * 8 + 4] =  sp * st;
        g[q * 8 + 5] =  cpl * ct; g[q * 8 + 6] =  spl * ct;
        g[q * 8 + 7] = 0.0f;
    }
    // ---- init mbarriers ----
    const uint32_t mbarBase = smem_u32(smem + OFF_MBAR);
    if (tid == 0) {
        #pragma unroll
        for (int s = 0; s < STAGES; s++)
            asm volatile("mbarrier.init.shared.b64 [%0], %1;"
                         :: "r"(mbarBase + 8 * s), "r"(1) : "memory");
    }
    __syncthreads();

    // ---- issue all 4 bulk copies (TMA pipe, zero register pressure) ----
    if (tid == 0) {
        const uint32_t tileBase = smem_u32(smem + OFF_TILE);
        const char* src = (const char*)(A + (size_t)blockIdx.x * ROWS_PER_BLK * KCOLS);
        #pragma unroll
        for (int s = 0; s < STAGES; s++) {
            const uint32_t mb = mbarBase + 8 * s;
            asm volatile("mbarrier.arrive.expect_tx.shared.b64 _, [%0], %1;"
                         :: "r"(mb), "r"(STAGE_BYTES) : "memory");
            asm volatile(
                "cp.async.bulk.shared::cta.global.mbarrier::complete_tx::bytes "
                "[%0], [%1], %2, [%3];"
                :: "r"(tileBase + s * STAGE_BYTES),
                   "l"(src + (size_t)s * STAGE_BYTES),
                   "r"(STAGE_BYTES), "r"(mb)
                : "memory");
        }
    }

    // ---- mainloop: 1 row per warp per stage, 32 lanes per row ----
    const float4* W0v = (const float4*)(Wf + 0 * KCOLS);
    const float4* W1v = (const float4*)(Wf + 1 * KCOLS);
    const float4* W2v = (const float4*)(Wf + 2 * KCOLS);
    const float4* W3v = (const float4*)(Wf + 3 * KCOLS);

    #pragma unroll
    for (int s = 0; s < STAGES; s++) {
        // wait stage s (parity 0; each barrier used once)
        {
            const uint32_t mb = mbarBase + 8 * s;
            asm volatile(
                "{\n\t.reg .pred P;\n\t"
                "W_%=:\n\t"
                "mbarrier.try_wait.parity.acquire.cta.shared::cta.b64 P, [%0], 0;\n\t"
                "@!P bra W_%=;\n\t}"
                :: "r"(mb) : "memory");
        }
        const int rowLocal = s * ROWS_PER_STAGE + warp;
        const float4* xrow = (const float4*)(smem + OFF_TILE + rowLocal * KCOLS * 4);

        float a0 = 0.f, a1 = 0.f, a2 = 0.f, a3 = 0.f;
        #pragma unroll
        for (int k = 0; k < 4; k++) {
            const int j = lane + 32 * k;         // consecutive lanes -> consecutive float4
            float4 x  = xrow[j];
            float4 w0 = W0v[j];
            float4 w1 = W1v[j];
            float4 w2 = W2v[j];
            float4 w3 = W3v[j];
            a0 += x.x * w0.x + x.y * w0.y + x.z * w0.z + x.w * w0.w;
            a1 += x.x * w1.x + x.y * w1.y + x.z * w1.z + x.w * w1.w;
            a2 += x.x * w2.x + x.y * w2.y + x.z * w2.z + x.w * w2.w;
            a3 += x.x * w3.x + x.y * w3.y + x.z * w3.z + x.w * w3.w;
        }
        #pragma unroll
        for (int off = 16; off; off >>= 1) {
            a0 += __shfl_xor_sync(0xffffffffu, a0, off);
            a1 += __shfl_xor_sync(0xffffffffu, a1, off);
            a2 += __shfl_xor_sync(0xffffffffu, a2, off);
            a3 += __shfl_xor_sync(0xffffffffu, a3, off);
        }
        if (lane == 0)
            preS[rowLocal] = make_float4(a0 + pre_b[0], a1 + pre_b[1],
                                         a2 + pre_b[2], a3 + pre_b[3]);
    }
    __syncthreads();

    // ---- circuit tail: warp 0, one row per lane (full lane efficiency) ----
    if (tid >= ROWS_PER_BLK) return;
    const int b = blockIdx.x * ROWS_PER_BLK + tid;
    if (b >= B) return;

    float4 p4 = preS[tid];
    float pre[NQ] = {p4.x, p4.y, p4.z, p4.w};

    float ryc[NQ], rys[NQ], rzc[NQ], rzs[NQ];
    #pragma unroll
    for (int q = 0; q < NQ; q++) {
        float t  = tanhf(pre[q] * 0.1f) * 1.5707963267948966f;
        float ry = atanf(t);
        float rz = atanf(t * t);
        __sincosf(0.5f * ry, &rys[q], &ryc[q]);
        __sincosf(0.5f * rz, &rzs[q], &rzc[q]);
    }

    float re[SDIM], im[SDIM];
    #pragma unroll
    for (int i = 0; i < SDIM; i++) { re[i] = 0.25f; im[i] = 0.0f; }

    // RY layer (state stays real)
    #pragma unroll
    for (int q = 0; q < NQ; q++) {
        const int bit = 8 >> q;
        const float c = ryc[q], s = rys[q];
        #pragma unroll
        for (int i = 0; i < SDIM; i++) {
            if (!(i & bit)) {
                float r0 = re[i], r1 = re[i | bit];
                re[i]       = c * r0 - s * r1;
                re[i | bit] = s * r0 + c * r1;
            }
        }
    }

    // RZ layer
    #pragma unroll
    for (int q = 0; q < NQ; q++) {
        const int bit = 8 >> q;
        const float c = rzc[q], sz = rzs[q];
        #pragma unroll
        for (int i = 0; i < SDIM; i++) {
            float s = (i & bit) ? sz : -sz;
            float r = re[i], m = im[i];
            re[i] = r * c - m * s;
            im[i] = r * s + m * c;
        }
    }

    // CNOT rings (register permutations)
    #define CNOT_(cq, tq)                                                  \
    {                                                                      \
        const int bc = 8 >> (cq), bt = 8 >> (tq);                          \
        _Pragma("unroll")                                                  \
        for (int i = 0; i < SDIM; i++) {                                   \
            if ((i & bc) && !(i & bt)) {                                   \
                float tr = re[i]; re[i] = re[i | bt]; re[i | bt] = tr;     \
                float tm = im[i]; im[i] = im[i | bt]; im[i | bt] = tm;     \
            }                                                              \
        }                                                                  \
    }
    CNOT_(0, 1); CNOT_(1, 2); CNOT_(2, 3); CNOT_(3, 0);
    CNOT_(0, 2); CNOT_(1, 3); CNOT_(2, 0); CNOT_(3, 1);
    #undef CNOT_

    // U3 layer
    #pragma unroll
    for (int q = 0; q < NQ; q++) {
        const int bit = 8 >> q;
        const float g00  = g[q * 8 + 0];
        const float g01r = g[q * 8 + 1], g01i = g[q * 8 + 2];
        const float g10r = g[q * 8 + 3], g10i = g[q * 8 + 4];
        const float g11r = g[q * 8 + 5], g11i = g[q * 8 + 6];
        #pragma unroll
        for (int i = 0; i < SDIM; i++) {
            if (!(i & bit)) {
                const int j = i | bit;
                float r0 = re[i], m0 = im[i], r1 = re[j], m1 = im[j];
                re[i] = g00 * r0 + g01r * r1 - g01i * m1;
                im[i] = g00 * m0 + g01r * m1 + g01i * r1;
                re[j] = g10r * r0 - g10i * m0 + g11r * r1 - g11i * m1;
                im[j] = g10r * m0 + g10i * r0 + g11r * m1 + g11i * r1;
            }
        }
    }

    // Z expectations
    float e0 = 0.f, e1 = 0.f, e2 = 0.f, e3 = 0.f;
    #pragma unroll
    for (int i = 0; i < SDIM; i++) {
        float p = re[i] * re[i] + im[i] * im[i];
        e0 += (i & 8) ? -p : p;
        e1 += (i & 4) ? -p : p;
        e2 += (i & 2) ? -p : p;
        e3 += (i & 1) ? -p : p;
    }

    float o0 = post_b[0] + e0 * post_w[0] + e1 * post_w[1] + e2 * post_w[2] + e3 * post_w[3];
    float o1 = post_b[1] + e0 * post_w[4] + e1 * post_w[5] + e2 * post_w[6] + e3 * post_w[7];
    ((float2*)out)[b] = make_float2(o0, o1);
}

extern "C" void kernel_launch(void* const* d_in, const int* in_sizes, int n_in,
                              void* d_out, int out_size) {
    const float* A      = (const float*)d_in[0];   // input_features [B,512]
    const float* pre_w  = (const float*)d_in[1];   // [4,512]
    const float* pre_b  = (const float*)d_in[2];   // [4]
    const float* u3p    = (const float*)d_in[3];   // [4,3]
    const float* post_w = (const float*)d_in[4];   // [2,4]
    const float* post_b = (const float*)d_in[5];   // [2]
    float* out          = (float*)d_out;           // [B,2]

    const int B = in_sizes[0] / KCOLS;

    static int configured = 0;
    if (!configured) {
        cudaFuncSetAttribute(qnet_tma_kernel,
                             cudaFuncAttributeMaxDynamicSharedMemorySize, SMEM_BYTES);
        configured = 1;
    }

    const int grid = (B + ROWS_PER_BLK - 1) / ROWS_PER_BLK;   // 1024
    qnet_tma_kernel<<<grid, TPB, SMEM_BYTES>>>(A, pre_w, pre_b, u3p,
                                               post_w, post_b, out, B);
}